// round 14
// baseline (speedup 1.0000x reference)
#include <cuda_runtime.h>
#include <cuda_bf16.h>
#include <math.h>
#include <string.h>

#define BB 16
#define SS 512
#define DD 128
#define HH 8
#define DKK 16
#define NCONV 4
#define KSZ 7
#define MROWS (BB*SS)
#define LN_EPS 1e-5f

typedef unsigned long long u64;
typedef unsigned int u32;

__device__ float g_x1 [MROWS*DD];
__device__ float g_qkv[MROWS*384];
__device__ float g_att[MROWS*DD];
__device__ float g_pos[SS*DD];       // precomputed positional signal
__device__ u32   g_wt [163840];

#define PW_OFF   0
#define QKV_OFF  65536
#define WO_OFF   114688
#define F1_OFF   131072
#define F2_OFF   147456

__device__ __forceinline__ u32 h2u(__nv_bfloat162 h) {
    u32 u; memcpy(&u, &h, 4); return u;
}
__device__ __forceinline__ void split2(float x, float y, u32& hi, u32& lo) {
    __nv_bfloat16 hx = __float2bfloat16(x);
    __nv_bfloat16 hy = __float2bfloat16(y);
    float rx = x - __bfloat162float(hx);
    float ry = y - __bfloat162float(hy);
    __nv_bfloat162 h; h.x = hx; h.y = hy;
    __nv_bfloat162 l; l.x = __float2bfloat16(rx); l.y = __float2bfloat16(ry);
    hi = h2u(h); lo = h2u(l);
}
__device__ __forceinline__ u32 pack_bf16x2(float x, float y) {
    u32 r; asm("cvt.rn.bf16x2.f32 %0, %1, %2;" : "=r"(r) : "f"(y), "f"(x)); return r;
}
__device__ __forceinline__ float possig(int st, int d) {
    const float inc = 9.210340371976184f / 63.0f;
    if (d < 64) return sinf((float)st * expf(-(float)d * inc));
    return cosf((float)st * expf(-(float)(d-64) * inc));
}

// ---------------- pos table fill (one tiny launch) -------------------------
__global__ void pos_fill_k() {
    int idx = blockIdx.x * blockDim.x + threadIdx.x;
    if (idx >= SS*DD) return;
    int s = idx >> 7, d = idx & 127;
    g_pos[idx] = possig(s, d);
}

// ---------------- weight prep (verbatim, verified) -------------------------
__device__ __forceinline__ float wsrc(int idx,
        const float* pw_w, const float* Wq, const float* Wk, const float* Wv,
        const float* Wo, const float* f1_w, const float* f2_w) {
    if (idx < QKV_OFF) return pw_w[idx];
    if (idx < WO_OFF) {
        int r = idx - QKV_OFF;
        int n = r >> 7, k = r & 127;
        int w = n >> 7, h = (n >> 4) & 7, kk = n & 15;
        const float* W = (w == 0) ? Wq : (w == 1) ? Wk : Wv;
        return W[(h*DD + k)*DKK + kk];
    }
    if (idx < F1_OFF) {
        int r = idx - WO_OFF;
        int n = r >> 7, k = r & 127;
        return Wo[k*DD + n];
    }
    if (idx < F2_OFF) return f1_w[idx - F1_OFF];
    return f2_w[idx - F2_OFF];
}

__global__ void prep_weights_k(const float* __restrict__ pw_w,
                               const float* __restrict__ Wq,
                               const float* __restrict__ Wk,
                               const float* __restrict__ Wv,
                               const float* __restrict__ Wo,
                               const float* __restrict__ f1_w,
                               const float* __restrict__ f2_w) {
    int p = blockIdx.x * blockDim.x + threadIdx.x;
    if (p >= 81920) return;
    int e = p * 2;
    float v0 = wsrc(e,   pw_w, Wq, Wk, Wv, Wo, f1_w, f2_w);
    float v1 = wsrc(e+1, pw_w, Wq, Wk, Wv, Wo, f1_w, f2_w);
    u32 hi, lo;
    split2(v0, v1, hi, lo);
    int base, losz, r;
    if (e < QKV_OFF)      { int unit = e >> 14; base = unit*16384; r = e & 16383; losz = 8192; }
    else if (e < WO_OFF)  { base = QKV_OFF; r = e - QKV_OFF; losz = 24576; }
    else if (e < F1_OFF)  { base = WO_OFF;  r = e - WO_OFF;  losz = 8192; }
    else if (e < F2_OFF)  { base = F1_OFF;  r = e - F1_OFF;  losz = 8192; }
    else                  { base = F2_OFF;  r = e - F2_OFF;  losz = 8192; }
    int n = r >> 7, kp = (r >> 1) & 63;
    g_wt[base + n*64 + kp]        = hi;
    g_wt[base + losz + n*64 + kp] = lo;
}

// ================= GEMM machinery ==========================================
#define H2S 68
#define MMA_BF16(acc, a, b) \
    asm volatile("mma.sync.aligned.m16n8k16.row.col.f32.bf16.bf16.f32 " \
        "{%0,%1,%2,%3}, {%4,%5,%6,%7}, {%8,%9}, {%0,%1,%2,%3};\n" \
        : "+f"(acc[0]), "+f"(acc[1]), "+f"(acc[2]), "+f"(acc[3]) \
        : "r"(a[0]), "r"(a[1]), "r"(a[2]), "r"(a[3]), "r"(b[0]), "r"(b[1]))

__device__ __forceinline__ void load_B(u32* Bh, u32* Bl,
        const u32* __restrict__ Whi, const u32* __restrict__ Wlo, int tid) {
    #pragma unroll
    for (int i = 0; i < 8; i++) {
        int idx = i*256 + tid;
        int r = idx >> 4, c4 = (idx & 15) << 2;
        *(uint4*)(Bh + r*H2S + c4) = *(const uint4*)(Whi + (size_t)r*64 + c4);
        *(uint4*)(Bl + r*H2S + c4) = *(const uint4*)(Wlo + (size_t)r*64 + c4);
    }
}

// 32-row M-tile main loop (conv / qkv / wo)
__device__ __forceinline__ void mma_main32(float acc[4][4],
        const u32* Ah, const u32* Al, const u32* Bh, const u32* Bl,
        int warpM, int warpN, int g, int tg) {
    #pragma unroll
    for (int kt = 0; kt < 8; kt++) {
        int kb = kt * 8;
        u32 ah[4], al[4], bh[4][2], bl[4][2];
        const u32* p = Ah + (warpM*16 + g)*H2S + kb + tg;
        ah[0] = p[0]; ah[1] = p[8*H2S]; ah[2] = p[4]; ah[3] = p[8*H2S + 4];
        const u32* q = Al + (warpM*16 + g)*H2S + kb + tg;
        al[0] = q[0]; al[1] = q[8*H2S]; al[2] = q[4]; al[3] = q[8*H2S + 4];
        #pragma unroll
        for (int ni = 0; ni < 4; ni++) {
            const u32* pb = Bh + (warpN*32 + ni*8 + g)*H2S + kb + tg;
            bh[ni][0] = pb[0]; bh[ni][1] = pb[4];
            const u32* qb = Bl + (warpN*32 + ni*8 + g)*H2S + kb + tg;
            bl[ni][0] = qb[0]; bl[ni][1] = qb[4];
        }
        #pragma unroll
        for (int ni = 0; ni < 4; ni++) {
            MMA_BF16(acc[ni], ah, bh[ni]);
            MMA_BF16(acc[ni], al, bh[ni]);
            MMA_BF16(acc[ni], ah, bl[ni]);
        }
    }
}

// 64-row version (FFN)
__device__ __forceinline__ void mma_main(float acc[2][4][4],
        const u32* Ah, const u32* Al, const u32* Bh, const u32* Bl,
        int warpM, int warpN, int g, int tg) {
    #pragma unroll
    for (int kt = 0; kt < 8; kt++) {
        int kb = kt * 8;
        u32 ah[2][4], al[2][4], bh[4][2], bl[4][2];
        #pragma unroll
        for (int mi = 0; mi < 2; mi++) {
            const u32* p = Ah + (warpM*32 + mi*16 + g)*H2S + kb + tg;
            ah[mi][0] = p[0]; ah[mi][1] = p[8*H2S]; ah[mi][2] = p[4]; ah[mi][3] = p[8*H2S + 4];
            const u32* q = Al + (warpM*32 + mi*16 + g)*H2S + kb + tg;
            al[mi][0] = q[0]; al[mi][1] = q[8*H2S]; al[mi][2] = q[4]; al[mi][3] = q[8*H2S + 4];
        }
        #pragma unroll
        for (int ni = 0; ni < 4; ni++) {
            const u32* p = Bh + (warpN*32 + ni*8 + g)*H2S + kb + tg;
            bh[ni][0] = p[0]; bh[ni][1] = p[4];
            const u32* q = Bl + (warpN*32 + ni*8 + g)*H2S + kb + tg;
            bl[ni][0] = q[0]; bl[ni][1] = q[4];
        }
        #pragma unroll
        for (int mi = 0; mi < 2; mi++)
            #pragma unroll
            for (int ni = 0; ni < 4; ni++) {
                MMA_BF16(acc[mi][ni], ah[mi], bh[ni]);
                MMA_BF16(acc[mi][ni], al[mi], bh[ni]);
                MMA_BF16(acc[mi][ni], ah[mi], bl[ni]);
            }
    }
}

// LN 32 tile rows (qkv)
__device__ __forceinline__ void ln_to_A32(u32* Ah, u32* Al,
        const float* __restrict__ X, int m0,
        const float* __restrict__ gamma, const float* __restrict__ beta,
        int warp, int lane) {
    float4 g4 = ((const float4*)gamma)[lane];
    float4 b4 = ((const float4*)beta)[lane];
    #pragma unroll
    for (int i = 0; i < 4; i++) {
        int r = warp*4 + i;
        float4 v = ((const float4*)(X + (size_t)(m0+r)*DD))[lane];
        float sum = v.x + v.y + v.z + v.w;
        #pragma unroll
        for (int o = 16; o; o >>= 1) sum += __shfl_xor_sync(0xffffffffu, sum, o);
        float mu = sum * (1.0f/128.0f);
        float dx = v.x-mu, dy = v.y-mu, dz = v.z-mu, dw = v.w-mu;
        float sq = dx*dx + dy*dy + dz*dz + dw*dw;
        #pragma unroll
        for (int o = 16; o; o >>= 1) sq += __shfl_xor_sync(0xffffffffu, sq, o);
        float rstd = rsqrtf(sq * (1.0f/128.0f) + LN_EPS);
        float nx = dx*rstd*g4.x + b4.x;
        float ny = dy*rstd*g4.y + b4.y;
        float nz = dz*rstd*g4.z + b4.z;
        float nw = dw*rstd*g4.w + b4.w;
        u32 h0, l0, h1, l1;
        split2(nx, ny, h0, l0);
        split2(nz, nw, h1, l1);
        int o2 = r*H2S + lane*2;
        Ah[o2] = h0; Ah[o2+1] = h1;
        Al[o2] = l0; Al[o2+1] = l1;
    }
}

// LN 64 tile rows (FFN)
__device__ __forceinline__ void ln_to_A(u32* Ah, u32* Al,
        const float* __restrict__ X, int m0,
        const float* __restrict__ gamma, const float* __restrict__ beta,
        int warp, int lane) {
    float4 g4 = ((const float4*)gamma)[lane];
    float4 b4 = ((const float4*)beta)[lane];
    #pragma unroll
    for (int i = 0; i < 8; i++) {
        int r = warp*8 + i;
        float4 v = ((const float4*)(X + (size_t)(m0+r)*DD))[lane];
        float sum = v.x + v.y + v.z + v.w;
        #pragma unroll
        for (int o = 16; o; o >>= 1) sum += __shfl_xor_sync(0xffffffffu, sum, o);
        float mu = sum * (1.0f/128.0f);
        float dx = v.x-mu, dy = v.y-mu, dz = v.z-mu, dw = v.w-mu;
        float sq = dx*dx + dy*dy + dz*dz + dw*dw;
        #pragma unroll
        for (int o = 16; o; o >>= 1) sq += __shfl_xor_sync(0xffffffffu, sq, o);
        float rstd = rsqrtf(sq * (1.0f/128.0f) + LN_EPS);
        float nx = dx*rstd*g4.x + b4.x;
        float ny = dy*rstd*g4.y + b4.y;
        float nz = dz*rstd*g4.z + b4.z;
        float nw = dw*rstd*g4.w + b4.w;
        u32 h0, l0, h1, l1;
        split2(nx, ny, h0, l0);
        split2(nz, nw, h1, l1);
        int o2 = r*H2S + lane*2;
        Ah[o2] = h0; Ah[o2+1] = h1;
        Al[o2] = l0; Al[o2+1] = l1;
    }
}

// ---------------- fused conv layer (pos via TABLE when ADDPOS) -------------
#define LNS 132
template<int ADDPOS>
__global__ __launch_bounds__(256) void conv_fused_k(
        const float* __restrict__ In, float* __restrict__ Out,
        const u32* __restrict__ Whi, const u32* __restrict__ Wlo,
        const float* __restrict__ gamma, const float* __restrict__ beta,
        const float* __restrict__ dw_w, const float* __restrict__ dw_b,
        const float* __restrict__ pw_b) {
    extern __shared__ u32 smg[];
    float* LNb = (float*)smg;            // [38][132]
    u32* Ah = smg + 38*LNS;              // [32][68]
    u32* Al = Ah + 32*H2S;
    u32* Bh = Al + 32*H2S;               // [128][68]
    u32* Bl = Bh + 128*H2S;

    int tid = threadIdx.x;
    int warp = tid >> 5, lane = tid & 31;
    int m0 = blockIdx.x * 32;
    int b = m0 >> 9, s0 = m0 & (SS-1);

    load_B(Bh, Bl, Whi, Wlo, tid);

    float4 g4 = ((const float4*)gamma)[lane];
    float4 be4 = ((const float4*)beta)[lane];
    #pragma unroll
    for (int it = 0; it < 5; it++) {
        int li = warp + it*8;
        if (li >= 38) break;
        int st = s0 - 3 + li;
        if ((unsigned)st < SS) {
            float4 v = ((const float4*)(In + (size_t)(b*SS+st)*DD))[lane];
            if (ADDPOS) {
                float4 pv = ((const float4*)(g_pos + (size_t)st*DD))[lane];
                v.x += pv.x; v.y += pv.y; v.z += pv.z; v.w += pv.w;
            }
            float sum = v.x + v.y + v.z + v.w;
            #pragma unroll
            for (int o = 16; o; o >>= 1) sum += __shfl_xor_sync(0xffffffffu, sum, o);
            float mu = sum * (1.0f/128.0f);
            float dx = v.x-mu, dy = v.y-mu, dz = v.z-mu, dw = v.w-mu;
            float sq = dx*dx + dy*dy + dz*dz + dw*dw;
            #pragma unroll
            for (int o = 16; o; o >>= 1) sq += __shfl_xor_sync(0xffffffffu, sq, o);
            float rstd = rsqrtf(sq * (1.0f/128.0f) + LN_EPS);
            float4 r;
            r.x = dx*rstd*g4.x + be4.x;
            r.y = dy*rstd*g4.y + be4.y;
            r.z = dz*rstd*g4.z + be4.z;
            r.w = dw*rstd*g4.w + be4.w;
            *(float4*)(LNb + li*LNS + lane*4) = r;
        }
    }
    __syncthreads();

    {
        int p = tid & 63, rq = tid >> 6;
        int c = 2*p;
        float w0[KSZ], w1[KSZ];
        #pragma unroll
        for (int j = 0; j < KSZ; j++) {
            w0[j] = dw_w[c*KSZ + j];
            w1[j] = dw_w[(c+1)*KSZ + j];
        }
        float bb0 = dw_b[c], bb1 = dw_b[c+1];
        #pragma unroll
        for (int i = 0; i < 8; i++) {
            int r = i*4 + rq;
            float a0 = bb0, a1 = bb1;
            #pragma unroll
            for (int j = 0; j < KSZ; j++) {
                int st = s0 + r - 3 + j;
                if ((unsigned)st < SS) {
                    float2 hv = *(const float2*)(LNb + (r+j)*LNS + c);
                    a0 += hv.x * w0[j];
                    a1 += hv.y * w1[j];
                }
            }
            u32 hi, lo;
            split2(a0, a1, hi, lo);
            Ah[r*H2S + p] = hi;
            Al[r*H2S + p] = lo;
        }
    }
    __syncthreads();

    int warpM = warp >> 2, warpN = warp & 3;
    int g = lane >> 2, tg = lane & 3;
    float acc[4][4];
    #pragma unroll
    for (int ni = 0; ni < 4; ni++)
        #pragma unroll
        for (int c = 0; c < 4; c++) acc[ni][c] = 0.0f;

    mma_main32(acc, Ah, Al, Bh, Bl, warpM, warpN, g, tg);

    #pragma unroll
    for (int ni = 0; ni < 4; ni++) {
        int col = warpN*32 + ni*8 + 2*tg;
        float2 bv = *(const float2*)(pw_b + col);
        int r0 = m0 + warpM*16 + g;
        float2 v0 = make_float2(fmaxf(acc[ni][0] + bv.x, 0.f),
                                fmaxf(acc[ni][1] + bv.y, 0.f));
        float2 v1 = make_float2(fmaxf(acc[ni][2] + bv.x, 0.f),
                                fmaxf(acc[ni][3] + bv.y, 0.f));
        float2 r0v = *(const float2*)(In + (size_t)r0*DD + col);
        float2 r1v = *(const float2*)(In + (size_t)(r0+8)*DD + col);
        if (ADDPOS) {
            int sA = r0 & (SS-1), sB = (r0+8) & (SS-1);
            float2 p0 = *(const float2*)(g_pos + (size_t)sA*DD + col);
            float2 p1 = *(const float2*)(g_pos + (size_t)sB*DD + col);
            r0v.x += p0.x; r0v.y += p0.y;
            r1v.x += p1.x; r1v.y += p1.y;
        }
        v0.x += r0v.x; v0.y += r0v.y;
        v1.x += r1v.x; v1.y += r1v.y;
        *(float2*)(Out + (size_t)r0*DD + col) = v0;
        *(float2*)(Out + (size_t)(r0+8)*DD + col) = v1;
    }
}

// ---------------- fused LN + QKV GEMM (verbatim) ---------------------------
__global__ __launch_bounds__(256) void qkv_fused_k(
        const float* __restrict__ In,
        const float* __restrict__ gamma, const float* __restrict__ beta,
        const float* __restrict__ att_bias, float* __restrict__ Outqkv) {
    extern __shared__ u32 smg[];
    u32* Ah = smg;
    u32* Al = Ah + 32*H2S;
    u32* Bh = Al + 32*H2S;
    u32* Bl = Bh + 128*H2S;
    int tid = threadIdx.x;
    int warp = tid >> 5, lane = tid & 31;
    int m0 = blockIdx.x * 32;
    int n0 = blockIdx.y * 128;

    load_B(Bh, Bl, g_wt + QKV_OFF + (size_t)(blockIdx.y)*128*64,
                   g_wt + QKV_OFF + 24576 + (size_t)(blockIdx.y)*128*64, tid);
    ln_to_A32(Ah, Al, In, m0, gamma, beta, warp, lane);
    __syncthreads();

    int warpM = warp >> 2, warpN = warp & 3;
    int g = lane >> 2, tg = lane & 3;
    float acc[4][4];
    #pragma unroll
    for (int ni = 0; ni < 4; ni++)
        #pragma unroll
        for (int c = 0; c < 4; c++) acc[ni][c] = 0.0f;

    mma_main32(acc, Ah, Al, Bh, Bl, warpM, warpN, g, tg);

    float b0 = att_bias[0];
    #pragma unroll
    for (int ni = 0; ni < 4; ni++) {
        int col = n0 + warpN*32 + ni*8 + 2*tg;
        int r0 = m0 + warpM*16 + g;
        float2 v0 = make_float2(acc[ni][0] + b0, acc[ni][1] + b0);
        float2 v1 = make_float2(acc[ni][2] + b0, acc[ni][3] + b0);
        *(float2*)(Outqkv + (size_t)r0*384 + col) = v0;
        *(float2*)(Outqkv + (size_t)(r0+8)*384 + col) = v1;
    }
}

// ---------------- Wo GEMM (verbatim) ---------------------------------------
__global__ __launch_bounds__(256) void wo_gemm_k(
        const float* __restrict__ A, const float* __restrict__ att_bias,
        const float* __restrict__ res, float* __restrict__ Out) {
    extern __shared__ u32 smg[];
    u32* Ah = smg;
    u32* Al = Ah + 32*H2S;
    u32* Bh = Al + 32*H2S;
    u32* Bl = Bh + 128*H2S;
    int tid = threadIdx.x;
    int warp = tid >> 5, lane = tid & 31;
    int m0 = blockIdx.x * 32;

    load_B(Bh, Bl, g_wt + WO_OFF, g_wt + WO_OFF + 8192, tid);
    #pragma unroll
    for (int i = 0; i < 4; i++) {
        int r = warp*4 + i;
        float4 v = ((const float4*)(A + (size_t)(m0+r)*DD))[lane];
        u32 h0, l0, h1, l1;
        split2(v.x, v.y, h0, l0);
        split2(v.z, v.w, h1, l1);
        int o2 = r*H2S + lane*2;
        Ah[o2] = h0; Ah[o2+1] = h1;
        Al[o2] = l0; Al[o2+1] = l1;
    }
    __syncthreads();

    int warpM = warp >> 2, warpN = warp & 3;
    int g = lane >> 2, tg = lane & 3;
    float acc[4][4];
    #pragma unroll
    for (int ni = 0; ni < 4; ni++)
        #pragma unroll
        for (int c = 0; c < 4; c++) acc[ni][c] = 0.0f;

    mma_main32(acc, Ah, Al, Bh, Bl, warpM, warpN, g, tg);

    float b0 = att_bias[0];
    #pragma unroll
    for (int ni = 0; ni < 4; ni++) {
        int col = warpN*32 + ni*8 + 2*tg;
        int r0 = m0 + warpM*16 + g;
        float2 r0v = *(const float2*)(res + (size_t)r0*DD + col);
        float2 r1v = *(const float2*)(res + (size_t)(r0+8)*DD + col);
        float2 v0 = make_float2(acc[ni][0] + b0 + r0v.x, acc[ni][1] + b0 + r0v.y);
        float2 v1 = make_float2(acc[ni][2] + b0 + r1v.x, acc[ni][3] + b0 + r1v.y);
        *(float2*)(Out + (size_t)r0*DD + col) = v0;
        *(float2*)(Out + (size_t)(r0+8)*DD + col) = v1;
    }
}

// ---------------- fused FFN (verbatim) -------------------------------------
__global__ __launch_bounds__(256) void ffn_fused_k(
        const float* __restrict__ In,
        const float* __restrict__ gamma, const float* __restrict__ beta,
        const float* __restrict__ f1_b, const float* __restrict__ f2_b,
        float* __restrict__ Out) {
    extern __shared__ u32 smg[];
    u32* Ah  = smg;
    u32* Al  = Ah + 64*H2S;
    u32* Bh1 = Al + 64*H2S;
    u32* Bl1 = Bh1 + 128*H2S;
    u32* Bh2 = Bl1 + 128*H2S;
    u32* Bl2 = Bh2 + 128*H2S;
    int tid = threadIdx.x;
    int warp = tid >> 5, lane = tid & 31;
    int m0 = blockIdx.x * 64;

    load_B(Bh1, Bl1, g_wt + F1_OFF, g_wt + F1_OFF + 8192, tid);
    load_B(Bh2, Bl2, g_wt + F2_OFF, g_wt + F2_OFF + 8192, tid);
    ln_to_A(Ah, Al, In, m0, gamma, beta, warp, lane);
    __syncthreads();

    int warpM = warp >> 2, warpN = warp & 3;
    int g = lane >> 2, tg = lane & 3;
    float acc[2][4][4];
    #pragma unroll
    for (int mi = 0; mi < 2; mi++)
        #pragma unroll
        for (int ni = 0; ni < 4; ni++)
            #pragma unroll
            for (int c = 0; c < 4; c++) acc[mi][ni][c] = 0.0f;

    mma_main(acc, Ah, Al, Bh1, Bl1, warpM, warpN, g, tg);
    __syncthreads();

    #pragma unroll
    for (int ni = 0; ni < 4; ni++) {
        int col = warpN*32 + ni*8 + 2*tg;
        float2 bv = *(const float2*)(f1_b + col);
        #pragma unroll
        for (int mi = 0; mi < 2; mi++) {
            int r = warpM*32 + mi*16 + g;
            float x0 = fmaxf(acc[mi][ni][0] + bv.x, 0.f);
            float y0 = fmaxf(acc[mi][ni][1] + bv.y, 0.f);
            float x1 = fmaxf(acc[mi][ni][2] + bv.x, 0.f);
            float y1 = fmaxf(acc[mi][ni][3] + bv.y, 0.f);
            u32 hi, lo;
            split2(x0, y0, hi, lo);
            Ah[r*H2S + (col>>1)] = hi; Al[r*H2S + (col>>1)] = lo;
            split2(x1, y1, hi, lo);
            Ah[(r+8)*H2S + (col>>1)] = hi; Al[(r+8)*H2S + (col>>1)] = lo;
        }
    }
    __syncthreads();

    #pragma unroll
    for (int mi = 0; mi < 2; mi++)
        #pragma unroll
        for (int ni = 0; ni < 4; ni++)
            #pragma unroll
            for (int c = 0; c < 4; c++) acc[mi][ni][c] = 0.0f;

    mma_main(acc, Ah, Al, Bh2, Bl2, warpM, warpN, g, tg);

    #pragma unroll
    for (int ni = 0; ni < 4; ni++) {
        int col = warpN*32 + ni*8 + 2*tg;
        float2 bv = *(const float2*)(f2_b + col);
        #pragma unroll
        for (int mi = 0; mi < 2; mi++) {
            int r0 = m0 + warpM*32 + mi*16 + g;
            float2 r0v = *(const float2*)(In + (size_t)r0*DD + col);
            float2 r1v = *(const float2*)(In + (size_t)(r0+8)*DD + col);
            float2 v0 = make_float2(acc[mi][ni][0] + bv.x + r0v.x, acc[mi][ni][1] + bv.y + r0v.y);
            float2 v1 = make_float2(acc[mi][ni][2] + bv.x + r1v.x, acc[mi][ni][3] + bv.y + r1v.y);
            *(float2*)(Out + (size_t)r0*DD + col) = v0;
            *(float2*)(Out + (size_t)(r0+8)*DD + col) = v1;
        }
    }
}

// ---------------- flash MMA attention: 2 q-tiles per block (verbatim R11) --
#define KSTR 12
#define VSTR 260
#define VSTG 20
__global__ __launch_bounds__(256) void attention_mma_k(
        const float* __restrict__ qkv, const int* __restrict__ mask,
        float* __restrict__ out) {
    extern __shared__ u32 smg[];
    u32* Khi  = smg;
    u32* Klo  = Khi + 512*KSTR;
    u32* Vthi = Klo + 512*KSTR;
    u32* Vtlo = Vthi + 16*VSTR;
    float* mb = (float*)(Vtlo + 16*VSTR);
    float* Vstage = mb + 512;

    int bh = blockIdx.x;
    int b = bh >> 3, h = bh & 7;
    int tid = threadIdx.x;
    int warp = tid >> 5, lane = tid & 31;
    int g = lane >> 2, tg = lane & 3;

    for (int idx = tid; idx < 512*4; idx += 256) {
        int t = idx >> 2, j = idx & 3;
        float4 kv = *(const float4*)(qkv + (size_t)(b*SS + t)*384 + 128 + h*DKK + j*4);
        u32 h0, l0, h1, l1;
        split2(kv.x, kv.y, h0, l0);
        split2(kv.z, kv.w, h1, l1);
        Khi[t*KSTR + 2*j]     = h0;  Khi[t*KSTR + 2*j + 1] = h1;
        Klo[t*KSTR + 2*j]     = l0;  Klo[t*KSTR + 2*j + 1] = l1;
    }
    for (int t = tid; t < SS; t += 256)
        mb[t] = mask[b*SS + t] ? 0.0f : -1e30f;

    #pragma unroll
    for (int half = 0; half < 2; half++) {
        __syncthreads();
        for (int idx = tid; idx < 256*4; idx += 256) {
            int key = idx >> 2, d4 = (idx & 3) * 4;
            float4 v = *(const float4*)(qkv + (size_t)(b*SS + half*256 + key)*384 + 256 + h*DKK + d4);
            *(float4*)(Vstage + key*VSTG + d4) = v;
        }
        __syncthreads();
        for (int idx = tid; idx < 16*128; idx += 256) {
            int kp = idx >> 4, d = idx & 15;
            float v0 = Vstage[(2*kp)*VSTG + d];
            float v1 = Vstage[(2*kp+1)*VSTG + d];
            u32 hi, lo;
            split2(v0, v1, hi, lo);
            Vthi[d*VSTR + half*128 + kp] = hi;
            Vtlo[d*VSTR + half*128 + kp] = lo;
        }
    }
    __syncthreads();

    for (int qg = 0; qg < 2; qg++) {
        int qrow = b*SS + blockIdx.y*256 + qg*128 + warp*16;
        u32 qh[4], ql[4];
        {
            const float* qp0 = qkv + (size_t)(qrow + g    )*384 + h*DKK;
            const float* qp1 = qkv + (size_t)(qrow + 8 + g)*384 + h*DKK;
            float2 A0 = *(const float2*)(qp0 + 2*tg);
            float2 A1 = *(const float2*)(qp1 + 2*tg);
            float2 A2 = *(const float2*)(qp0 + 2*tg + 8);
            float2 A3 = *(const float2*)(qp1 + 2*tg + 8);
            split2(A0.x, A0.y, qh[0], ql[0]);
            split2(A1.x, A1.y, qh[1], ql[1]);
            split2(A2.x, A2.y, qh[2], ql[2]);
            split2(A3.x, A3.y, qh[3], ql[3]);
        }

        float m0 = -1e30f, m1 = -1e30f, l0 = 0.f, l1 = 0.f;
        float o[2][4];
        #pragma unroll
        for (int vd = 0; vd < 2; vd++)
            #pragma unroll
            for (int c = 0; c < 4; c++) o[vd][c] = 0.f;

        #pragma unroll
        for (int c = 0; c < 4; c++) {
            int k0 = c * 128;
            float s[16][4];
            #pragma unroll
            for (int nt = 0; nt < 16; nt++) {
                s[nt][0] = s[nt][1] = s[nt][2] = s[nt][3] = 0.f;
                int t = k0 + nt*8 + g;
                u32 kh[2], kl[2];
                kh[0] = Khi[t*KSTR + tg];  kh[1] = Khi[t*KSTR + tg + 4];
                kl[0] = Klo[t*KSTR + tg];  kl[1] = Klo[t*KSTR + tg + 4];
                MMA_BF16(s[nt], qh, kh);
                MMA_BF16(s[nt], ql, kh);
                MMA_BF16(s[nt], qh, kl);
            }
            float cm0 = -1e30f, cm1 = -1e30f;
            #pragma unroll
            for (int nt = 0; nt < 16; nt++) {
                float2 mv = *(const float2*)(mb + k0 + nt*8 + 2*tg);
                s[nt][0] = s[nt][0]*0.25f + mv.x;
                s[nt][1] = s[nt][1]*0.25f + mv.y;
                s[nt][2] = s[nt][2]*0.25f + mv.x;
                s[nt][3] = s[nt][3]*0.25f + mv.y;
                cm0 = fmaxf(cm0, fmaxf(s[nt][0], s[nt][1]));
                cm1 = fmaxf(cm1, fmaxf(s[nt][2], s[nt][3]));
            }
            cm0 = fmaxf(cm0, __shfl_xor_sync(0xffffffffu, cm0, 1));
            cm0 = fmaxf(cm0, __shfl_xor_sync(0xffffffffu, cm0, 2));
            cm1 = fmaxf(cm1, __shfl_xor_sync(0xffffffffu, cm1, 1));
            cm1 = fmaxf(cm1, __shfl_xor_sync(0xffffffffu, cm1, 2));
            float nm0 = fmaxf(m0, cm0), nm1 = fmaxf(m1, cm1);
            float al0 = __expf(m0 - nm0), al1 = __expf(m1 - nm1);
            m0 = nm0; m1 = nm1;
            #pragma unroll
            for (int vd = 0; vd < 2; vd++) {
                o[vd][0] *= al0; o[vd][1] *= al0;
                o[vd][2] *= al1; o[vd][3] *= al1;
            }
            float ls0 = 0.f, ls1 = 0.f;
            #pragma unroll
            for (int nt = 0; nt < 16; nt++) {
                s[nt][0] = __expf(s[nt][0] - nm0);
                s[nt][1] = __expf(s[nt][1] - nm0);
                s[nt][2] = __expf(s[nt][2] - nm1);
                s[nt][3] = __expf(s[nt][3] - nm1);
                ls0 += s[nt][0] + s[nt][1];
                ls1 += s[nt][2] + s[nt][3];
            }
            ls0 += __shfl_xor_sync(0xffffffffu, ls0, 1);
            ls0 += __shfl_xor_sync(0xffffffffu, ls0, 2);
            ls1 += __shfl_xor_sync(0xffffffffu, ls1, 1);
            ls1 += __shfl_xor_sync(0xffffffffu, ls1, 2);
            l0 = al0*l0 + ls0;
            l1 = al1*l1 + ls1;
            #pragma unroll
            for (int kc = 0; kc < 8; kc++) {
                u32 ph[4];
                ph[0] = pack_bf16x2(s[2*kc][0],   s[2*kc][1]);
                ph[1] = pack_bf16x2(s[2*kc][2],   s[2*kc][3]);
                ph[2] = pack_bf16x2(s[2*kc+1][0], s[2*kc+1][1]);
                ph[3] = pack_bf16x2(s[2*kc+1][2], s[2*kc+1][3]);
                #pragma unroll
                for (int vd = 0; vd < 2; vd++) {
                    int vr = (vd*8 + g)*VSTR + c*64 + kc*8 + tg;
                    u32 vh[2], vl[2];
                    vh[0] = Vthi[vr];  vh[1] = Vthi[vr + 4];
                    vl[0] = Vtlo[vr];  vl[1] = Vtlo[vr + 4];
                    MMA_BF16(o[vd], ph, vh);
                    MMA_BF16(o[vd], ph, vl);
                }
            }
        }

        float inv0 = 1.0f / l0, inv1 = 1.0f / l1;
        #pragma unroll
        for (int vd = 0; vd < 2; vd++) {
            int col = h*DKK + vd*8 + 2*tg;
            *(float2*)(out + (size_t)(qrow + g    )*DD + col) =
                make_float2(o[vd][0]*inv0, o[vd][1]*inv0);
            *(float2*)(out + (size_t)(qrow + 8 + g)*DD + col) =
                make_float2(o[vd][2]*inv1, o[vd][3]*inv1);
        }
    }
}

// ---------------- host launcher --------------------------------------------
extern "C" void kernel_launch(void* const* d_in, const int* in_sizes, int n_in,
                              void* d_out, int out_size) {
    const float* x        = (const float*)d_in[0];
    const int*   mask     = (const int*)  d_in[1];
    const float* ln_scale = (const float*)d_in[2];
    const float* ln_bias  = (const float*)d_in[3];
    const float* dw_w     = (const float*)d_in[4];
    const float* dw_b     = (const float*)d_in[5];
    const float* pw_w     = (const float*)d_in[6];
    const float* pw_b     = (const float*)d_in[7];
    const float* Wq       = (const float*)d_in[8];
    const float* Wk       = (const float*)d_in[9];
    const float* Wv       = (const float*)d_in[10];
    const float* Wo       = (const float*)d_in[11];
    const float* att_bias = (const float*)d_in[12];
    const float* f1_w     = (const float*)d_in[13];
    const float* f1_b     = (const float*)d_in[14];
    const float* f2_w     = (const float*)d_in[15];
    const float* f2_b     = (const float*)d_in[16];
    float* out = (float*)d_out;

    float *px1, *pqkv, *patt;
    u32 *pwt;
    cudaGetSymbolAddress((void**)&px1,  g_x1);
    cudaGetSymbolAddress((void**)&pqkv, g_qkv);
    cudaGetSymbolAddress((void**)&patt, g_att);
    cudaGetSymbolAddress((void**)&pwt,  g_wt);

    const int CONV_SMEM = (38*LNS)*4 + (32*H2S*2 + 128*H2S*2)*4;   // 107,168
    const int GEMM_SMEM = (32*H2S*2 + 128*H2S*2)*4;                // 87,040
    const int FFN_SMEM  = (64*H2S*2 + 128*H2S*2*2)*4;              // 174,080
    const int ASMEM     = (2*512*KSTR + 2*16*VSTR + 512 + 256*VSTG)*4;  // 104,960
    cudaFuncSetAttribute(conv_fused_k<0>, cudaFuncAttributeMaxDynamicSharedMemorySize, CONV_SMEM);
    cudaFuncSetAttribute(conv_fused_k<1>, cudaFuncAttributeMaxDynamicSharedMemorySize, CONV_SMEM);
    cudaFuncSetAttribute(qkv_fused_k,     cudaFuncAttributeMaxDynamicSharedMemorySize, GEMM_SMEM);
    cudaFuncSetAttribute(wo_gemm_k,       cudaFuncAttributeMaxDynamicSharedMemorySize, GEMM_SMEM);
    cudaFuncSetAttribute(ffn_fused_k,     cudaFuncAttributeMaxDynamicSharedMemorySize, FFN_SMEM);
    cudaFuncSetAttribute(attention_mma_k, cudaFuncAttributeMaxDynamicSharedMemorySize, ASMEM);

    pos_fill_k<<<256, 256>>>();
    prep_weights_k<<<320, 256>>>(pw_w, Wq, Wk, Wv, Wo, f1_w, f2_w);

    // conv stack (layer 0 adds pos table, reads x): x->T1->T0->T1->T0(out)
    {
        const u32* w0 = pwt + PW_OFF;
        conv_fused_k<1><<<256, 256, CONV_SMEM>>>(
            x, px1, w0, w0 + 8192,
            ln_scale, ln_bias, dw_w, dw_b, pw_b);
    }
    float* bufs[2] = { px1, out };
    for (int i = 1; i < NCONV; i++) {
        const u32* whi = pwt + PW_OFF + (size_t)i*16384;
        conv_fused_k<0><<<256, 256, CONV_SMEM>>>(
            bufs[(i-1) & 1], bufs[i & 1], whi, whi + 8192,
            ln_scale + i*DD, ln_bias + i*DD,
            dw_w + (size_t)i*DD*KSZ, dw_b + i*DD, pw_b + i*DD);
    }
    // final conv output in bufs[1] = out

    qkv_fused_k<<<dim3(256,3), 256, GEMM_SMEM>>>(
        out, ln_scale + NCONV*DD, ln_bias + NCONV*DD, att_bias, pqkv);
    attention_mma_k<<<dim3(BB*HH, 2), 256, ASMEM>>>(pqkv, mask, patt);
    wo_gemm_k<<<256, 256, GEMM_SMEM>>>(patt, att_bias, out, px1);

    ffn_fused_k<<<128, 256, FFN_SMEM>>>(
        px1, ln_scale + (NCONV+1)*DD, ln_bias + (NCONV+1)*DD, f1_b, f2_b, out);
}

// round 15
// speedup vs baseline: 1.5049x; 1.5049x over previous
#include <cuda_runtime.h>
#include <cuda_bf16.h>
#include <math.h>
#include <string.h>

#define BB 16
#define SS 512
#define DD 128
#define HH 8
#define DKK 16
#define NCONV 4
#define KSZ 7
#define MROWS (BB*SS)
#define LN_EPS 1e-5f

typedef unsigned long long u64;
typedef unsigned int u32;

__device__ float g_x1 [MROWS*DD];
__device__ float g_qkv[MROWS*384];
__device__ float g_att[MROWS*DD];
__device__ float g_pos[SS*DD];       // precomputed positional signal
__device__ u32   g_wt [163840];

#define PW_OFF   0
#define QKV_OFF  65536
#define WO_OFF   114688
#define F1_OFF   131072
#define F2_OFF   147456

__device__ __forceinline__ u32 h2u(__nv_bfloat162 h) {
    u32 u; memcpy(&u, &h, 4); return u;
}
__device__ __forceinline__ void split2(float x, float y, u32& hi, u32& lo) {
    __nv_bfloat16 hx = __float2bfloat16(x);
    __nv_bfloat16 hy = __float2bfloat16(y);
    float rx = x - __bfloat162float(hx);
    float ry = y - __bfloat162float(hy);
    __nv_bfloat162 h; h.x = hx; h.y = hy;
    __nv_bfloat162 l; l.x = __float2bfloat16(rx); l.y = __float2bfloat16(ry);
    hi = h2u(h); lo = h2u(l);
}
__device__ __forceinline__ u32 pack_bf16x2(float x, float y) {
    u32 r; asm("cvt.rn.bf16x2.f32 %0, %1, %2;" : "=r"(r) : "f"(y), "f"(x)); return r;
}
__device__ __forceinline__ float possig(int st, int d) {
    const float inc = 9.210340371976184f / 63.0f;
    if (d < 64) return sinf((float)st * expf(-(float)d * inc));
    return cosf((float)st * expf(-(float)(d-64) * inc));
}

// ---------------- weight prep + pos table (merged, one launch) -------------
__device__ __forceinline__ float wsrc(int idx,
        const float* pw_w, const float* Wq, const float* Wk, const float* Wv,
        const float* Wo, const float* f1_w, const float* f2_w) {
    if (idx < QKV_OFF) return pw_w[idx];
    if (idx < WO_OFF) {
        int r = idx - QKV_OFF;
        int n = r >> 7, k = r & 127;
        int w = n >> 7, h = (n >> 4) & 7, kk = n & 15;
        const float* W = (w == 0) ? Wq : (w == 1) ? Wk : Wv;
        return W[(h*DD + k)*DKK + kk];
    }
    if (idx < F1_OFF) {
        int r = idx - WO_OFF;
        int n = r >> 7, k = r & 127;
        return Wo[k*DD + n];
    }
    if (idx < F2_OFF) return f1_w[idx - F1_OFF];
    return f2_w[idx - F2_OFF];
}

__global__ void prep_weights_k(const float* __restrict__ pw_w,
                               const float* __restrict__ Wq,
                               const float* __restrict__ Wk,
                               const float* __restrict__ Wv,
                               const float* __restrict__ Wo,
                               const float* __restrict__ f1_w,
                               const float* __restrict__ f2_w) {
    int p = blockIdx.x * blockDim.x + threadIdx.x;
    if (p >= 81920) {
        int idx = p - 81920;                 // pos table: 65536 entries
        if (idx < SS*DD) {
            int s = idx >> 7, d = idx & 127;
            g_pos[idx] = possig(s, d);
        }
        return;
    }
    int e = p * 2;
    float v0 = wsrc(e,   pw_w, Wq, Wk, Wv, Wo, f1_w, f2_w);
    float v1 = wsrc(e+1, pw_w, Wq, Wk, Wv, Wo, f1_w, f2_w);
    u32 hi, lo;
    split2(v0, v1, hi, lo);
    int base, losz, r;
    if (e < QKV_OFF)      { int unit = e >> 14; base = unit*16384; r = e & 16383; losz = 8192; }
    else if (e < WO_OFF)  { base = QKV_OFF; r = e - QKV_OFF; losz = 24576; }
    else if (e < F1_OFF)  { base = WO_OFF;  r = e - WO_OFF;  losz = 8192; }
    else if (e < F2_OFF)  { base = F1_OFF;  r = e - F1_OFF;  losz = 8192; }
    else                  { base = F2_OFF;  r = e - F2_OFF;  losz = 8192; }
    int n = r >> 7, kp = (r >> 1) & 63;
    g_wt[base + n*64 + kp]        = hi;
    g_wt[base + losz + n*64 + kp] = lo;
}

// ================= GEMM machinery ==========================================
#define H2S 68
#define MMA_BF16(acc, a, b) \
    asm volatile("mma.sync.aligned.m16n8k16.row.col.f32.bf16.bf16.f32 " \
        "{%0,%1,%2,%3}, {%4,%5,%6,%7}, {%8,%9}, {%0,%1,%2,%3};\n" \
        : "+f"(acc[0]), "+f"(acc[1]), "+f"(acc[2]), "+f"(acc[3]) \
        : "r"(a[0]), "r"(a[1]), "r"(a[2]), "r"(a[3]), "r"(b[0]), "r"(b[1]))

__device__ __forceinline__ void load_B(u32* Bh, u32* Bl,
        const u32* __restrict__ Whi, const u32* __restrict__ Wlo, int tid) {
    #pragma unroll
    for (int i = 0; i < 8; i++) {
        int idx = i*256 + tid;
        int r = idx >> 4, c4 = (idx & 15) << 2;
        *(uint4*)(Bh + r*H2S + c4) = *(const uint4*)(Whi + (size_t)r*64 + c4);
        *(uint4*)(Bl + r*H2S + c4) = *(const uint4*)(Wlo + (size_t)r*64 + c4);
    }
}

// 32-row M-tile main loop (conv / qkv / wo)
__device__ __forceinline__ void mma_main32(float acc[4][4],
        const u32* Ah, const u32* Al, const u32* Bh, const u32* Bl,
        int warpM, int warpN, int g, int tg) {
    #pragma unroll
    for (int kt = 0; kt < 8; kt++) {
        int kb = kt * 8;
        u32 ah[4], al[4], bh[4][2], bl[4][2];
        const u32* p = Ah + (warpM*16 + g)*H2S + kb + tg;
        ah[0] = p[0]; ah[1] = p[8*H2S]; ah[2] = p[4]; ah[3] = p[8*H2S + 4];
        const u32* q = Al + (warpM*16 + g)*H2S + kb + tg;
        al[0] = q[0]; al[1] = q[8*H2S]; al[2] = q[4]; al[3] = q[8*H2S + 4];
        #pragma unroll
        for (int ni = 0; ni < 4; ni++) {
            const u32* pb = Bh + (warpN*32 + ni*8 + g)*H2S + kb + tg;
            bh[ni][0] = pb[0]; bh[ni][1] = pb[4];
            const u32* qb = Bl + (warpN*32 + ni*8 + g)*H2S + kb + tg;
            bl[ni][0] = qb[0]; bl[ni][1] = qb[4];
        }
        #pragma unroll
        for (int ni = 0; ni < 4; ni++) {
            MMA_BF16(acc[ni], ah, bh[ni]);
            MMA_BF16(acc[ni], al, bh[ni]);
            MMA_BF16(acc[ni], ah, bl[ni]);
        }
    }
}

// 64-row version (FFN)
__device__ __forceinline__ void mma_main(float acc[2][4][4],
        const u32* Ah, const u32* Al, const u32* Bh, const u32* Bl,
        int warpM, int warpN, int g, int tg) {
    #pragma unroll
    for (int kt = 0; kt < 8; kt++) {
        int kb = kt * 8;
        u32 ah[2][4], al[2][4], bh[4][2], bl[4][2];
        #pragma unroll
        for (int mi = 0; mi < 2; mi++) {
            const u32* p = Ah + (warpM*32 + mi*16 + g)*H2S + kb + tg;
            ah[mi][0] = p[0]; ah[mi][1] = p[8*H2S]; ah[mi][2] = p[4]; ah[mi][3] = p[8*H2S + 4];
            const u32* q = Al + (warpM*32 + mi*16 + g)*H2S + kb + tg;
            al[mi][0] = q[0]; al[mi][1] = q[8*H2S]; al[mi][2] = q[4]; al[mi][3] = q[8*H2S + 4];
        }
        #pragma unroll
        for (int ni = 0; ni < 4; ni++) {
            const u32* p = Bh + (warpN*32 + ni*8 + g)*H2S + kb + tg;
            bh[ni][0] = p[0]; bh[ni][1] = p[4];
            const u32* q = Bl + (warpN*32 + ni*8 + g)*H2S + kb + tg;
            bl[ni][0] = q[0]; bl[ni][1] = q[4];
        }
        #pragma unroll
        for (int mi = 0; mi < 2; mi++)
            #pragma unroll
            for (int ni = 0; ni < 4; ni++) {
                MMA_BF16(acc[mi][ni], ah[mi], bh[ni]);
                MMA_BF16(acc[mi][ni], al[mi], bh[ni]);
                MMA_BF16(acc[mi][ni], ah[mi], bl[ni]);
            }
    }
}

// LN 32 tile rows (qkv)
__device__ __forceinline__ void ln_to_A32(u32* Ah, u32* Al,
        const float* __restrict__ X, int m0,
        const float* __restrict__ gamma, const float* __restrict__ beta,
        int warp, int lane) {
    float4 g4 = ((const float4*)gamma)[lane];
    float4 b4 = ((const float4*)beta)[lane];
    #pragma unroll
    for (int i = 0; i < 4; i++) {
        int r = warp*4 + i;
        float4 v = ((const float4*)(X + (size_t)(m0+r)*DD))[lane];
        float sum = v.x + v.y + v.z + v.w;
        #pragma unroll
        for (int o = 16; o; o >>= 1) sum += __shfl_xor_sync(0xffffffffu, sum, o);
        float mu = sum * (1.0f/128.0f);
        float dx = v.x-mu, dy = v.y-mu, dz = v.z-mu, dw = v.w-mu;
        float sq = dx*dx + dy*dy + dz*dz + dw*dw;
        #pragma unroll
        for (int o = 16; o; o >>= 1) sq += __shfl_xor_sync(0xffffffffu, sq, o);
        float rstd = rsqrtf(sq * (1.0f/128.0f) + LN_EPS);
        float nx = dx*rstd*g4.x + b4.x;
        float ny = dy*rstd*g4.y + b4.y;
        float nz = dz*rstd*g4.z + b4.z;
        float nw = dw*rstd*g4.w + b4.w;
        u32 h0, l0, h1, l1;
        split2(nx, ny, h0, l0);
        split2(nz, nw, h1, l1);
        int o2 = r*H2S + lane*2;
        Ah[o2] = h0; Ah[o2+1] = h1;
        Al[o2] = l0; Al[o2+1] = l1;
    }
}

// LN 64 tile rows (FFN)
__device__ __forceinline__ void ln_to_A(u32* Ah, u32* Al,
        const float* __restrict__ X, int m0,
        const float* __restrict__ gamma, const float* __restrict__ beta,
        int warp, int lane) {
    float4 g4 = ((const float4*)gamma)[lane];
    float4 b4 = ((const float4*)beta)[lane];
    #pragma unroll
    for (int i = 0; i < 8; i++) {
        int r = warp*8 + i;
        float4 v = ((const float4*)(X + (size_t)(m0+r)*DD))[lane];
        float sum = v.x + v.y + v.z + v.w;
        #pragma unroll
        for (int o = 16; o; o >>= 1) sum += __shfl_xor_sync(0xffffffffu, sum, o);
        float mu = sum * (1.0f/128.0f);
        float dx = v.x-mu, dy = v.y-mu, dz = v.z-mu, dw = v.w-mu;
        float sq = dx*dx + dy*dy + dz*dz + dw*dw;
        #pragma unroll
        for (int o = 16; o; o >>= 1) sq += __shfl_xor_sync(0xffffffffu, sq, o);
        float rstd = rsqrtf(sq * (1.0f/128.0f) + LN_EPS);
        float nx = dx*rstd*g4.x + b4.x;
        float ny = dy*rstd*g4.y + b4.y;
        float nz = dz*rstd*g4.z + b4.z;
        float nw = dw*rstd*g4.w + b4.w;
        u32 h0, l0, h1, l1;
        split2(nx, ny, h0, l0);
        split2(nz, nw, h1, l1);
        int o2 = r*H2S + lane*2;
        Ah[o2] = h0; Ah[o2+1] = h1;
        Al[o2] = l0; Al[o2+1] = l1;
    }
}

// ---------------- fused conv layer (pos via TABLE when ADDPOS) -------------
#define LNS 132
template<int ADDPOS>
__global__ __launch_bounds__(256) void conv_fused_k(
        const float* __restrict__ In, float* __restrict__ Out,
        const u32* __restrict__ Whi, const u32* __restrict__ Wlo,
        const float* __restrict__ gamma, const float* __restrict__ beta,
        const float* __restrict__ dw_w, const float* __restrict__ dw_b,
        const float* __restrict__ pw_b) {
    extern __shared__ u32 smg[];
    float* LNb = (float*)smg;            // [38][132]
    u32* Ah = smg + 38*LNS;              // [32][68]
    u32* Al = Ah + 32*H2S;
    u32* Bh = Al + 32*H2S;               // [128][68]
    u32* Bl = Bh + 128*H2S;

    int tid = threadIdx.x;
    int warp = tid >> 5, lane = tid & 31;
    int m0 = blockIdx.x * 32;
    int b = m0 >> 9, s0 = m0 & (SS-1);

    load_B(Bh, Bl, Whi, Wlo, tid);

    float4 g4 = ((const float4*)gamma)[lane];
    float4 be4 = ((const float4*)beta)[lane];
    #pragma unroll
    for (int it = 0; it < 5; it++) {
        int li = warp + it*8;
        if (li >= 38) break;
        int st = s0 - 3 + li;
        if ((unsigned)st < SS) {
            float4 v = ((const float4*)(In + (size_t)(b*SS+st)*DD))[lane];
            if (ADDPOS) {
                float4 pv = ((const float4*)(g_pos + (size_t)st*DD))[lane];
                v.x += pv.x; v.y += pv.y; v.z += pv.z; v.w += pv.w;
            }
            float sum = v.x + v.y + v.z + v.w;
            #pragma unroll
            for (int o = 16; o; o >>= 1) sum += __shfl_xor_sync(0xffffffffu, sum, o);
            float mu = sum * (1.0f/128.0f);
            float dx = v.x-mu, dy = v.y-mu, dz = v.z-mu, dw = v.w-mu;
            float sq = dx*dx + dy*dy + dz*dz + dw*dw;
            #pragma unroll
            for (int o = 16; o; o >>= 1) sq += __shfl_xor_sync(0xffffffffu, sq, o);
            float rstd = rsqrtf(sq * (1.0f/128.0f) + LN_EPS);
            float4 r;
            r.x = dx*rstd*g4.x + be4.x;
            r.y = dy*rstd*g4.y + be4.y;
            r.z = dz*rstd*g4.z + be4.z;
            r.w = dw*rstd*g4.w + be4.w;
            *(float4*)(LNb + li*LNS + lane*4) = r;
        }
    }
    __syncthreads();

    {
        int p = tid & 63, rq = tid >> 6;
        int c = 2*p;
        float w0[KSZ], w1[KSZ];
        #pragma unroll
        for (int j = 0; j < KSZ; j++) {
            w0[j] = dw_w[c*KSZ + j];
            w1[j] = dw_w[(c+1)*KSZ + j];
        }
        float bb0 = dw_b[c], bb1 = dw_b[c+1];
        #pragma unroll
        for (int i = 0; i < 8; i++) {
            int r = i*4 + rq;
            float a0 = bb0, a1 = bb1;
            #pragma unroll
            for (int j = 0; j < KSZ; j++) {
                int st = s0 + r - 3 + j;
                if ((unsigned)st < SS) {
                    float2 hv = *(const float2*)(LNb + (r+j)*LNS + c);
                    a0 += hv.x * w0[j];
                    a1 += hv.y * w1[j];
                }
            }
            u32 hi, lo;
            split2(a0, a1, hi, lo);
            Ah[r*H2S + p] = hi;
            Al[r*H2S + p] = lo;
        }
    }
    __syncthreads();

    int warpM = warp >> 2, warpN = warp & 3;
    int g = lane >> 2, tg = lane & 3;
    float acc[4][4];
    #pragma unroll
    for (int ni = 0; ni < 4; ni++)
        #pragma unroll
        for (int c = 0; c < 4; c++) acc[ni][c] = 0.0f;

    mma_main32(acc, Ah, Al, Bh, Bl, warpM, warpN, g, tg);

    #pragma unroll
    for (int ni = 0; ni < 4; ni++) {
        int col = warpN*32 + ni*8 + 2*tg;
        float2 bv = *(const float2*)(pw_b + col);
        int r0 = m0 + warpM*16 + g;
        float2 v0 = make_float2(fmaxf(acc[ni][0] + bv.x, 0.f),
                                fmaxf(acc[ni][1] + bv.y, 0.f));
        float2 v1 = make_float2(fmaxf(acc[ni][2] + bv.x, 0.f),
                                fmaxf(acc[ni][3] + bv.y, 0.f));
        float2 r0v = *(const float2*)(In + (size_t)r0*DD + col);
        float2 r1v = *(const float2*)(In + (size_t)(r0+8)*DD + col);
        if (ADDPOS) {
            int sA = r0 & (SS-1), sB = (r0+8) & (SS-1);
            float2 p0 = *(const float2*)(g_pos + (size_t)sA*DD + col);
            float2 p1 = *(const float2*)(g_pos + (size_t)sB*DD + col);
            r0v.x += p0.x; r0v.y += p0.y;
            r1v.x += p1.x; r1v.y += p1.y;
        }
        v0.x += r0v.x; v0.y += r0v.y;
        v1.x += r1v.x; v1.y += r1v.y;
        *(float2*)(Out + (size_t)r0*DD + col) = v0;
        *(float2*)(Out + (size_t)(r0+8)*DD + col) = v1;
    }
}

// ---------------- fused LN + QKV GEMM --------------------------------------
__global__ __launch_bounds__(256) void qkv_fused_k(
        const float* __restrict__ In,
        const float* __restrict__ gamma, const float* __restrict__ beta,
        const float* __restrict__ att_bias, float* __restrict__ Outqkv) {
    extern __shared__ u32 smg[];
    u32* Ah = smg;
    u32* Al = Ah + 32*H2S;
    u32* Bh = Al + 32*H2S;
    u32* Bl = Bh + 128*H2S;
    int tid = threadIdx.x;
    int warp = tid >> 5, lane = tid & 31;
    int m0 = blockIdx.x * 32;
    int n0 = blockIdx.y * 128;

    load_B(Bh, Bl, g_wt + QKV_OFF + (size_t)(blockIdx.y)*128*64,
                   g_wt + QKV_OFF + 24576 + (size_t)(blockIdx.y)*128*64, tid);
    ln_to_A32(Ah, Al, In, m0, gamma, beta, warp, lane);
    __syncthreads();

    int warpM = warp >> 2, warpN = warp & 3;
    int g = lane >> 2, tg = lane & 3;
    float acc[4][4];
    #pragma unroll
    for (int ni = 0; ni < 4; ni++)
        #pragma unroll
        for (int c = 0; c < 4; c++) acc[ni][c] = 0.0f;

    mma_main32(acc, Ah, Al, Bh, Bl, warpM, warpN, g, tg);

    float b0 = att_bias[0];
    #pragma unroll
    for (int ni = 0; ni < 4; ni++) {
        int col = n0 + warpN*32 + ni*8 + 2*tg;
        int r0 = m0 + warpM*16 + g;
        float2 v0 = make_float2(acc[ni][0] + b0, acc[ni][1] + b0);
        float2 v1 = make_float2(acc[ni][2] + b0, acc[ni][3] + b0);
        *(float2*)(Outqkv + (size_t)r0*384 + col) = v0;
        *(float2*)(Outqkv + (size_t)(r0+8)*384 + col) = v1;
    }
}

// ---------------- Wo GEMM --------------------------------------------------
__global__ __launch_bounds__(256) void wo_gemm_k(
        const float* __restrict__ A, const float* __restrict__ att_bias,
        const float* __restrict__ res, float* __restrict__ Out) {
    extern __shared__ u32 smg[];
    u32* Ah = smg;
    u32* Al = Ah + 32*H2S;
    u32* Bh = Al + 32*H2S;
    u32* Bl = Bh + 128*H2S;
    int tid = threadIdx.x;
    int warp = tid >> 5, lane = tid & 31;
    int m0 = blockIdx.x * 32;

    load_B(Bh, Bl, g_wt + WO_OFF, g_wt + WO_OFF + 8192, tid);
    #pragma unroll
    for (int i = 0; i < 4; i++) {
        int r = warp*4 + i;
        float4 v = ((const float4*)(A + (size_t)(m0+r)*DD))[lane];
        u32 h0, l0, h1, l1;
        split2(v.x, v.y, h0, l0);
        split2(v.z, v.w, h1, l1);
        int o2 = r*H2S + lane*2;
        Ah[o2] = h0; Ah[o2+1] = h1;
        Al[o2] = l0; Al[o2+1] = l1;
    }
    __syncthreads();

    int warpM = warp >> 2, warpN = warp & 3;
    int g = lane >> 2, tg = lane & 3;
    float acc[4][4];
    #pragma unroll
    for (int ni = 0; ni < 4; ni++)
        #pragma unroll
        for (int c = 0; c < 4; c++) acc[ni][c] = 0.0f;

    mma_main32(acc, Ah, Al, Bh, Bl, warpM, warpN, g, tg);

    float b0 = att_bias[0];
    #pragma unroll
    for (int ni = 0; ni < 4; ni++) {
        int col = warpN*32 + ni*8 + 2*tg;
        int r0 = m0 + warpM*16 + g;
        float2 r0v = *(const float2*)(res + (size_t)r0*DD + col);
        float2 r1v = *(const float2*)(res + (size_t)(r0+8)*DD + col);
        float2 v0 = make_float2(acc[ni][0] + b0 + r0v.x, acc[ni][1] + b0 + r0v.y);
        float2 v1 = make_float2(acc[ni][2] + b0 + r1v.x, acc[ni][3] + b0 + r1v.y);
        *(float2*)(Out + (size_t)r0*DD + col) = v0;
        *(float2*)(Out + (size_t)(r0+8)*DD + col) = v1;
    }
}

// ---------------- fused FFN ------------------------------------------------
__global__ __launch_bounds__(256) void ffn_fused_k(
        const float* __restrict__ In,
        const float* __restrict__ gamma, const float* __restrict__ beta,
        const float* __restrict__ f1_b, const float* __restrict__ f2_b,
        float* __restrict__ Out) {
    extern __shared__ u32 smg[];
    u32* Ah  = smg;
    u32* Al  = Ah + 64*H2S;
    u32* Bh1 = Al + 64*H2S;
    u32* Bl1 = Bh1 + 128*H2S;
    u32* Bh2 = Bl1 + 128*H2S;
    u32* Bl2 = Bh2 + 128*H2S;
    int tid = threadIdx.x;
    int warp = tid >> 5, lane = tid & 31;
    int m0 = blockIdx.x * 64;

    load_B(Bh1, Bl1, g_wt + F1_OFF, g_wt + F1_OFF + 8192, tid);
    load_B(Bh2, Bl2, g_wt + F2_OFF, g_wt + F2_OFF + 8192, tid);
    ln_to_A(Ah, Al, In, m0, gamma, beta, warp, lane);
    __syncthreads();

    int warpM = warp >> 2, warpN = warp & 3;
    int g = lane >> 2, tg = lane & 3;
    float acc[2][4][4];
    #pragma unroll
    for (int mi = 0; mi < 2; mi++)
        #pragma unroll
        for (int ni = 0; ni < 4; ni++)
            #pragma unroll
            for (int c = 0; c < 4; c++) acc[mi][ni][c] = 0.0f;

    mma_main(acc, Ah, Al, Bh1, Bl1, warpM, warpN, g, tg);
    __syncthreads();

    #pragma unroll
    for (int ni = 0; ni < 4; ni++) {
        int col = warpN*32 + ni*8 + 2*tg;
        float2 bv = *(const float2*)(f1_b + col);
        #pragma unroll
        for (int mi = 0; mi < 2; mi++) {
            int r = warpM*32 + mi*16 + g;
            float x0 = fmaxf(acc[mi][ni][0] + bv.x, 0.f);
            float y0 = fmaxf(acc[mi][ni][1] + bv.y, 0.f);
            float x1 = fmaxf(acc[mi][ni][2] + bv.x, 0.f);
            float y1 = fmaxf(acc[mi][ni][3] + bv.y, 0.f);
            u32 hi, lo;
            split2(x0, y0, hi, lo);
            Ah[r*H2S + (col>>1)] = hi; Al[r*H2S + (col>>1)] = lo;
            split2(x1, y1, hi, lo);
            Ah[(r+8)*H2S + (col>>1)] = hi; Al[(r+8)*H2S + (col>>1)] = lo;
        }
    }
    __syncthreads();

    #pragma unroll
    for (int mi = 0; mi < 2; mi++)
        #pragma unroll
        for (int ni = 0; ni < 4; ni++)
            #pragma unroll
            for (int c = 0; c < 4; c++) acc[mi][ni][c] = 0.0f;

    mma_main(acc, Ah, Al, Bh2, Bl2, warpM, warpN, g, tg);

    #pragma unroll
    for (int ni = 0; ni < 4; ni++) {
        int col = warpN*32 + ni*8 + 2*tg;
        float2 bv = *(const float2*)(f2_b + col);
        #pragma unroll
        for (int mi = 0; mi < 2; mi++) {
            int r0 = m0 + warpM*32 + mi*16 + g;
            float2 r0v = *(const float2*)(In + (size_t)r0*DD + col);
            float2 r1v = *(const float2*)(In + (size_t)(r0+8)*DD + col);
            float2 v0 = make_float2(acc[mi][ni][0] + bv.x + r0v.x, acc[mi][ni][1] + bv.y + r0v.y);
            float2 v1 = make_float2(acc[mi][ni][2] + bv.x + r1v.x, acc[mi][ni][3] + bv.y + r1v.y);
            *(float2*)(Out + (size_t)r0*DD + col) = v0;
            *(float2*)(Out + (size_t)(r0+8)*DD + col) = v1;
        }
    }
}

// ---------------- flash MMA attention: 2 q-tiles per block -----------------
#define KSTR 12
#define VSTR 260
#define VSTG 20
__global__ __launch_bounds__(256) void attention_mma_k(
        const float* __restrict__ qkv, const int* __restrict__ mask,
        float* __restrict__ out) {
    extern __shared__ u32 smg[];
    u32* Khi  = smg;
    u32* Klo  = Khi + 512*KSTR;
    u32* Vthi = Klo + 512*KSTR;
    u32* Vtlo = Vthi + 16*VSTR;
    float* mb = (float*)(Vtlo + 16*VSTR);
    float* Vstage = mb + 512;

    int bh = blockIdx.x;
    int b = bh >> 3, h = bh & 7;
    int tid = threadIdx.x;
    int warp = tid >> 5, lane = tid & 31;
    int g = lane >> 2, tg = lane & 3;

    for (int idx = tid; idx < 512*4; idx += 256) {
        int t = idx >> 2, j = idx & 3;
        float4 kv = *(const float4*)(qkv + (size_t)(b*SS + t)*384 + 128 + h*DKK + j*4);
        u32 h0, l0, h1, l1;
        split2(kv.x, kv.y, h0, l0);
        split2(kv.z, kv.w, h1, l1);
        Khi[t*KSTR + 2*j]     = h0;  Khi[t*KSTR + 2*j + 1] = h1;
        Klo[t*KSTR + 2*j]     = l0;  Klo[t*KSTR + 2*j + 1] = l1;
    }
    for (int t = tid; t < SS; t += 256)
        mb[t] = mask[b*SS + t] ? 0.0f : -1e30f;

    #pragma unroll
    for (int half = 0; half < 2; half++) {
        __syncthreads();
        for (int idx = tid; idx < 256*4; idx += 256) {
            int key = idx >> 2, d4 = (idx & 3) * 4;
            float4 v = *(const float4*)(qkv + (size_t)(b*SS + half*256 + key)*384 + 256 + h*DKK + d4);
            *(float4*)(Vstage + key*VSTG + d4) = v;
        }
        __syncthreads();
        for (int idx = tid; idx < 16*128; idx += 256) {
            int kp = idx >> 4, d = idx & 15;
            float v0 = Vstage[(2*kp)*VSTG + d];
            float v1 = Vstage[(2*kp+1)*VSTG + d];
            u32 hi, lo;
            split2(v0, v1, hi, lo);
            Vthi[d*VSTR + half*128 + kp] = hi;
            Vtlo[d*VSTR + half*128 + kp] = lo;
        }
    }
    __syncthreads();

    for (int qg = 0; qg < 2; qg++) {
        int qrow = b*SS + blockIdx.y*256 + qg*128 + warp*16;
        u32 qh[4], ql[4];
        {
            const float* qp0 = qkv + (size_t)(qrow + g    )*384 + h*DKK;
            const float* qp1 = qkv + (size_t)(qrow + 8 + g)*384 + h*DKK;
            float2 A0 = *(const float2*)(qp0 + 2*tg);
            float2 A1 = *(const float2*)(qp1 + 2*tg);
            float2 A2 = *(const float2*)(qp0 + 2*tg + 8);
            float2 A3 = *(const float2*)(qp1 + 2*tg + 8);
            split2(A0.x, A0.y, qh[0], ql[0]);
            split2(A1.x, A1.y, qh[1], ql[1]);
            split2(A2.x, A2.y, qh[2], ql[2]);
            split2(A3.x, A3.y, qh[3], ql[3]);
        }

        float m0 = -1e30f, m1 = -1e30f, l0 = 0.f, l1 = 0.f;
        float o[2][4];
        #pragma unroll
        for (int vd = 0; vd < 2; vd++)
            #pragma unroll
            for (int c = 0; c < 4; c++) o[vd][c] = 0.f;

        #pragma unroll
        for (int c = 0; c < 4; c++) {
            int k0 = c * 128;
            float s[16][4];
            #pragma unroll
            for (int nt = 0; nt < 16; nt++) {
                s[nt][0] = s[nt][1] = s[nt][2] = s[nt][3] = 0.f;
                int t = k0 + nt*8 + g;
                u32 kh[2], kl[2];
                kh[0] = Khi[t*KSTR + tg];  kh[1] = Khi[t*KSTR + tg + 4];
                kl[0] = Klo[t*KSTR + tg];  kl[1] = Klo[t*KSTR + tg + 4];
                MMA_BF16(s[nt], qh, kh);
                MMA_BF16(s[nt], ql, kh);
                MMA_BF16(s[nt], qh, kl);
            }
            float cm0 = -1e30f, cm1 = -1e30f;
            #pragma unroll
            for (int nt = 0; nt < 16; nt++) {
                float2 mv = *(const float2*)(mb + k0 + nt*8 + 2*tg);
                s[nt][0] = s[nt][0]*0.25f + mv.x;
                s[nt][1] = s[nt][1]*0.25f + mv.y;
                s[nt][2] = s[nt][2]*0.25f + mv.x;
                s[nt][3] = s[nt][3]*0.25f + mv.y;
                cm0 = fmaxf(cm0, fmaxf(s[nt][0], s[nt][1]));
                cm1 = fmaxf(cm1, fmaxf(s[nt][2], s[nt][3]));
            }
            cm0 = fmaxf(cm0, __shfl_xor_sync(0xffffffffu, cm0, 1));
            cm0 = fmaxf(cm0, __shfl_xor_sync(0xffffffffu, cm0, 2));
            cm1 = fmaxf(cm1, __shfl_xor_sync(0xffffffffu, cm1, 1));
            cm1 = fmaxf(cm1, __shfl_xor_sync(0xffffffffu, cm1, 2));
            float nm0 = fmaxf(m0, cm0), nm1 = fmaxf(m1, cm1);
            float al0 = __expf(m0 - nm0), al1 = __expf(m1 - nm1);
            m0 = nm0; m1 = nm1;
            #pragma unroll
            for (int vd = 0; vd < 2; vd++) {
                o[vd][0] *= al0; o[vd][1] *= al0;
                o[vd][2] *= al1; o[vd][3] *= al1;
            }
            float ls0 = 0.f, ls1 = 0.f;
            #pragma unroll
            for (int nt = 0; nt < 16; nt++) {
                s[nt][0] = __expf(s[nt][0] - nm0);
                s[nt][1] = __expf(s[nt][1] - nm0);
                s[nt][2] = __expf(s[nt][2] - nm1);
                s[nt][3] = __expf(s[nt][3] - nm1);
                ls0 += s[nt][0] + s[nt][1];
                ls1 += s[nt][2] + s[nt][3];
            }
            ls0 += __shfl_xor_sync(0xffffffffu, ls0, 1);
            ls0 += __shfl_xor_sync(0xffffffffu, ls0, 2);
            ls1 += __shfl_xor_sync(0xffffffffu, ls1, 1);
            ls1 += __shfl_xor_sync(0xffffffffu, ls1, 2);
            l0 = al0*l0 + ls0;
            l1 = al1*l1 + ls1;
            #pragma unroll
            for (int kc = 0; kc < 8; kc++) {
                u32 ph[4];
                ph[0] = pack_bf16x2(s[2*kc][0],   s[2*kc][1]);
                ph[1] = pack_bf16x2(s[2*kc][2],   s[2*kc][3]);
                ph[2] = pack_bf16x2(s[2*kc+1][0], s[2*kc+1][1]);
                ph[3] = pack_bf16x2(s[2*kc+1][2], s[2*kc+1][3]);
                #pragma unroll
                for (int vd = 0; vd < 2; vd++) {
                    int vr = (vd*8 + g)*VSTR + c*64 + kc*8 + tg;
                    u32 vh[2], vl[2];
                    vh[0] = Vthi[vr];  vh[1] = Vthi[vr + 4];
                    vl[0] = Vtlo[vr];  vl[1] = Vtlo[vr + 4];
                    MMA_BF16(o[vd], ph, vh);
                    MMA_BF16(o[vd], ph, vl);
                }
            }
        }

        float inv0 = 1.0f / l0, inv1 = 1.0f / l1;
        #pragma unroll
        for (int vd = 0; vd < 2; vd++) {
            int col = h*DKK + vd*8 + 2*tg;
            *(float2*)(out + (size_t)(qrow + g    )*DD + col) =
                make_float2(o[vd][0]*inv0, o[vd][1]*inv0);
            *(float2*)(out + (size_t)(qrow + 8 + g)*DD + col) =
                make_float2(o[vd][2]*inv1, o[vd][3]*inv1);
        }
    }
}

// ---------------- host launcher --------------------------------------------
extern "C" void kernel_launch(void* const* d_in, const int* in_sizes, int n_in,
                              void* d_out, int out_size) {
    const float* x        = (const float*)d_in[0];
    const int*   mask     = (const int*)  d_in[1];
    const float* ln_scale = (const float*)d_in[2];
    const float* ln_bias  = (const float*)d_in[3];
    const float* dw_w     = (const float*)d_in[4];
    const float* dw_b     = (const float*)d_in[5];
    const float* pw_w     = (const float*)d_in[6];
    const float* pw_b     = (const float*)d_in[7];
    const float* Wq       = (const float*)d_in[8];
    const float* Wk       = (const float*)d_in[9];
    const float* Wv       = (const float*)d_in[10];
    const float* Wo       = (const float*)d_in[11];
    const float* att_bias = (const float*)d_in[12];
    const float* f1_w     = (const float*)d_in[13];
    const float* f1_b     = (const float*)d_in[14];
    const float* f2_w     = (const float*)d_in[15];
    const float* f2_b     = (const float*)d_in[16];
    float* out = (float*)d_out;

    float *px1, *pqkv, *patt;
    u32 *pwt;
    cudaGetSymbolAddress((void**)&px1,  g_x1);
    cudaGetSymbolAddress((void**)&pqkv, g_qkv);
    cudaGetSymbolAddress((void**)&patt, g_att);
    cudaGetSymbolAddress((void**)&pwt,  g_wt);

    const int CONV_SMEM = (38*LNS)*4 + (32*H2S*2 + 128*H2S*2)*4;   // 107,168
    const int GEMM_SMEM = (32*H2S*2 + 128*H2S*2)*4;                // 87,040
    const int FFN_SMEM  = (64*H2S*2 + 128*H2S*2*2)*4;              // 174,080
    const int ASMEM     = (2*512*KSTR + 2*16*VSTR + 512 + 256*VSTG)*4;  // 104,960
    cudaFuncSetAttribute(conv_fused_k<0>, cudaFuncAttributeMaxDynamicSharedMemorySize, CONV_SMEM);
    cudaFuncSetAttribute(conv_fused_k<1>, cudaFuncAttributeMaxDynamicSharedMemorySize, CONV_SMEM);
    cudaFuncSetAttribute(qkv_fused_k,     cudaFuncAttributeMaxDynamicSharedMemorySize, GEMM_SMEM);
    cudaFuncSetAttribute(wo_gemm_k,       cudaFuncAttributeMaxDynamicSharedMemorySize, GEMM_SMEM);
    cudaFuncSetAttribute(ffn_fused_k,     cudaFuncAttributeMaxDynamicSharedMemorySize, FFN_SMEM);
    cudaFuncSetAttribute(attention_mma_k, cudaFuncAttributeMaxDynamicSharedMemorySize, ASMEM);

    // weights + pos table in one launch (576 blocks: 320 weights + 256 pos)
    prep_weights_k<<<576, 256>>>(pw_w, Wq, Wk, Wv, Wo, f1_w, f2_w);

    // conv stack (layer 0 adds pos table, reads x): x->T1->T0->T1->T0(out)
    {
        const u32* w0 = pwt + PW_OFF;
        conv_fused_k<1><<<256, 256, CONV_SMEM>>>(
            x, px1, w0, w0 + 8192,
            ln_scale, ln_bias, dw_w, dw_b, pw_b);
    }
    float* bufs[2] = { px1, out };
    for (int i = 1; i < NCONV; i++) {
        const u32* whi = pwt + PW_OFF + (size_t)i*16384;
        conv_fused_k<0><<<256, 256, CONV_SMEM>>>(
            bufs[(i-1) & 1], bufs[i & 1], whi, whi + 8192,
            ln_scale + i*DD, ln_bias + i*DD,
            dw_w + (size_t)i*DD*KSZ, dw_b + i*DD, pw_b + i*DD);
    }
    // final conv output in bufs[1] = out

    qkv_fused_k<<<dim3(256,3), 256, GEMM_SMEM>>>(
        out, ln_scale + NCONV*DD, ln_bias + NCONV*DD, att_bias, pqkv);
    attention_mma_k<<<dim3(BB*HH, 2), 256, ASMEM>>>(pqkv, mask, patt);
    wo_gemm_k<<<256, 256, GEMM_SMEM>>>(patt, att_bias, out, px1);

    ffn_fused_k<<<128, 256, FFN_SMEM>>>(
        px1, ln_scale + (NCONV+1)*DD, ln_bias + (NCONV+1)*DD, f1_b, f2_b, out);
}